// round 6
// baseline (speedup 1.0000x reference)
#include <cuda_runtime.h>
#include <math.h>

// Problem constants (fixed by the reference build)
#define MM   4096      // checks
#define NN   8192      // variables
#define BB   256       // batch
#define EE   32768     // edges  (NN * DV)
#define N_ITERS 10
#define ALPHA_C 0.8f
#define CLAMP_V 20.0f
#define PAD_BIG_C 1.0e6f

// ---------------- static device scratch (no allocations allowed) -----------
__device__ float g_ctv  [EE * BB];   // check->var messages, edge-major [E,B]
__device__ float g_vtc  [EE * BB];   // clamped var->check messages, [E,B]
__device__ float g_llr_t[NN * BB];   // transposed channel LLR, [N,B]
__device__ float g_ssign[MM * BB];   // 1-2*syndrome, [M,B]
__device__ float g_hard [NN * BB];   // hard decisions, [N,B] (for parity)
__device__ int   g_deg  [MM];        // check degrees
__device__ int   g_ce   [MM * 32];   // per check: compacted edge ids
__device__ int   g_cv   [MM * 32];   // per check: compacted var ids (parity)

// ---------------- helpers ----------------------------------------------------
__device__ __forceinline__ float clampv(float x) {
    return fminf(fmaxf(x, -CLAMP_V), CLAMP_V);
}

// ---------------- kernels ---------------------------------------------------
// Device globals referenced only from device code (host shadow is not a dev ptr).

// Transpose llr [B,N] -> g_llr_t [N,B]; also seed g_vtc (iter0 ctv==0 so
// vtc[e] = clamp(llr[v]) for each of v's 4 edges).
__global__ void k_tr_llr(const float* __restrict__ in,
                         const int* __restrict__ var_adj)
{
    __shared__ float tile[32][33];
    int c0 = blockIdx.x * 32;   // N tile
    int r0 = blockIdx.y * 32;   // B tile
    int c = c0 + threadIdx.x;
    #pragma unroll
    for (int i = 0; i < 32; i += 8) {
        int r = r0 + threadIdx.y + i;
        tile[threadIdx.y + i][threadIdx.x] = in[(size_t)r * NN + c];
    }
    __syncthreads();
    int oc = r0 + threadIdx.x;            // batch index
    #pragma unroll
    for (int i = 0; i < 32; i += 8) {
        int v = c0 + threadIdx.y + i;     // var index (uniform per warp)
        float x = tile[threadIdx.x][threadIdx.y + i];
        g_llr_t[(size_t)v * BB + oc] = x;
        float cv = clampv(x);
        int4 e = __ldg((const int4*)var_adj + v);
        g_vtc[(size_t)e.x * BB + oc] = cv;
        g_vtc[(size_t)e.y * BB + oc] = cv;
        g_vtc[(size_t)e.z * BB + oc] = cv;
        g_vtc[(size_t)e.w * BB + oc] = cv;
    }
}

// Transpose syndrome [B,M] -> g_ssign [M,B] with 1-2x.
__global__ void k_tr_syn(const float* __restrict__ in)
{
    __shared__ float tile[32][33];
    int c0 = blockIdx.x * 32;
    int r0 = blockIdx.y * 32;
    int c = c0 + threadIdx.x;
    #pragma unroll
    for (int i = 0; i < 32; i += 8) {
        int r = r0 + threadIdx.y + i;
        tile[threadIdx.y + i][threadIdx.x] = in[(size_t)r * MM + c];
    }
    __syncthreads();
    int oc = r0 + threadIdx.x;
    #pragma unroll
    for (int i = 0; i < 32; i += 8) {
        int orow = c0 + threadIdx.y + i;
        g_ssign[(size_t)orow * BB + oc] =
            1.0f - 2.0f * tile[threadIdx.x][threadIdx.y + i];
    }
}

// Prep: per-check degree + compacted edge/var slot tables.
__global__ void k_prep(const float* __restrict__ check_mask,
                       const int* __restrict__ check_adj,
                       const int* __restrict__ var_idx,
                       int max_dc)
{
    int c = blockIdx.x * blockDim.x + threadIdx.x;
    if (c >= MM) return;
    const float* m   = check_mask + (size_t)c * max_dc;
    const int*   adj = check_adj  + (size_t)c * max_dc;
    int d = 0;
    for (int j = 0; j < max_dc; j++) {
        if (__ldg(m + j) != 0.0f) {
            int e = __ldg(adj + j);
            g_ce[c * 32 + d] = e;
            g_cv[c * 32 + d] = __ldg(var_idx + e);
            d++;
        }
    }
    g_deg[c] = d;
}

// Check-side min-sum, slot-parallel.
// Block = 256 threads = one check, 32 batch-quads (2 blocks per check).
// Warp layout: lane bits [4:2] = slot group (0..7), bits [1:0] = batch quad.
// Each thread owns slots p = sgp + 8k (k<4, deg<=32); x stays in registers,
// min1/min2/sign reduced across slot groups with 3 butterfly shuffles.
__global__ void k_checkupd()
{
    int c = blockIdx.x >> 1;
    int deg = g_deg[c];
    if (deg == 0) return;
    int t = threadIdx.x;
    int lane = t & 31;
    int w = t >> 5;
    int sgp = lane >> 2;                                   // slot group
    int j = ((blockIdx.x & 1) << 5) + (w << 2) + (lane & 3); // batch quad

    const int* ce = g_ce + c * 32;
    int e0 = (sgp      < deg) ? ce[sgp]      : -1;
    int e1 = (sgp + 8  < deg) ? ce[sgp + 8]  : -1;
    int e2 = (sgp + 16 < deg) ? ce[sgp + 16] : -1;
    int e3 = (sgp + 24 < deg) ? ce[sgp + 24] : -1;

    float4 x0 = make_float4(0,0,0,0), x1 = x0, x2 = x0, x3 = x0;
    if (e0 >= 0) x0 = ((const float4*)(g_vtc + (size_t)e0 * BB))[j];
    if (e1 >= 0) x1 = ((const float4*)(g_vtc + (size_t)e1 * BB))[j];
    if (e2 >= 0) x2 = ((const float4*)(g_vtc + (size_t)e2 * BB))[j];
    if (e3 >= 0) x3 = ((const float4*)(g_vtc + (size_t)e3 * BB))[j];

    float4 m1 = make_float4(1e30f, 1e30f, 1e30f, 1e30f);
    float4 m2 = m1;
    float4 sg = make_float4(1.f, 1.f, 1.f, 1.f);

#define ACC(X, E)                                                             \
    if ((E) >= 0) {                                                           \
        float a;                                                              \
        if ((X).x < 0.f) sg.x = -sg.x;                                        \
        if ((X).y < 0.f) sg.y = -sg.y;                                        \
        if ((X).z < 0.f) sg.z = -sg.z;                                        \
        if ((X).w < 0.f) sg.w = -sg.w;                                        \
        a = fabsf((X).x); if (a < m1.x) { m2.x = m1.x; m1.x = a; } else if (a < m2.x) m2.x = a; \
        a = fabsf((X).y); if (a < m1.y) { m2.y = m1.y; m1.y = a; } else if (a < m2.y) m2.y = a; \
        a = fabsf((X).z); if (a < m1.z) { m2.z = m1.z; m1.z = a; } else if (a < m2.z) m2.z = a; \
        a = fabsf((X).w); if (a < m1.w) { m2.w = m1.w; m1.w = a; } else if (a < m2.w) m2.w = a; \
    }
    ACC(x0, e0) ACC(x1, e1) ACC(x2, e2) ACC(x3, e3)
#undef ACC

    // butterfly reduction across slot groups (lane bits 2..4)
    #pragma unroll
    for (int ofs = 4; ofs < 32; ofs <<= 1) {
        float4 o1, o2, os;
        o1.x = __shfl_xor_sync(0xffffffffu, m1.x, ofs);
        o1.y = __shfl_xor_sync(0xffffffffu, m1.y, ofs);
        o1.z = __shfl_xor_sync(0xffffffffu, m1.z, ofs);
        o1.w = __shfl_xor_sync(0xffffffffu, m1.w, ofs);
        o2.x = __shfl_xor_sync(0xffffffffu, m2.x, ofs);
        o2.y = __shfl_xor_sync(0xffffffffu, m2.y, ofs);
        o2.z = __shfl_xor_sync(0xffffffffu, m2.z, ofs);
        o2.w = __shfl_xor_sync(0xffffffffu, m2.w, ofs);
        os.x = __shfl_xor_sync(0xffffffffu, sg.x, ofs);
        os.y = __shfl_xor_sync(0xffffffffu, sg.y, ofs);
        os.z = __shfl_xor_sync(0xffffffffu, sg.z, ofs);
        os.w = __shfl_xor_sync(0xffffffffu, sg.w, ofs);
        m2.x = fminf(fminf(m2.x, o2.x), fmaxf(m1.x, o1.x)); m1.x = fminf(m1.x, o1.x);
        m2.y = fminf(fminf(m2.y, o2.y), fmaxf(m1.y, o1.y)); m1.y = fminf(m1.y, o1.y);
        m2.z = fminf(fminf(m2.z, o2.z), fmaxf(m1.z, o1.z)); m1.z = fminf(m1.z, o1.z);
        m2.w = fminf(fminf(m2.w, o2.w), fmaxf(m1.w, o1.w)); m1.w = fminf(m1.w, o1.w);
        sg.x *= os.x; sg.y *= os.y; sg.z *= os.z; sg.w *= os.w;
    }

    float4 ss = ((const float4*)(g_ssign + (size_t)c * BB))[j];
    sg.x *= ss.x; sg.y *= ss.y; sg.z *= ss.z; sg.w *= ss.w;

    if (deg == 1) {
        // reference pads with global edge 0: min2 = |vtc(edge0)| + 1e6
        float4 p0 = ((const float4*)g_vtc)[j];   // row 0, already clamped
        m2.x = fabsf(p0.x) + PAD_BIG_C;
        m2.y = fabsf(p0.y) + PAD_BIG_C;
        m2.z = fabsf(p0.z) + PAD_BIG_C;
        m2.w = fabsf(p0.w) + PAD_BIG_C;
    }

#define EMIT(X, E)                                                            \
    if ((E) >= 0) {                                                           \
        float4 o; float a, m;                                                 \
        a = fabsf((X).x); m = (fabsf(a - m1.x) < 1e-9f) ? m2.x : m1.x;        \
        o.x = ALPHA_C * sg.x * (((X).x < 0.f) ? -m : m);                      \
        a = fabsf((X).y); m = (fabsf(a - m1.y) < 1e-9f) ? m2.y : m1.y;        \
        o.y = ALPHA_C * sg.y * (((X).y < 0.f) ? -m : m);                      \
        a = fabsf((X).z); m = (fabsf(a - m1.z) < 1e-9f) ? m2.z : m1.z;        \
        o.z = ALPHA_C * sg.z * (((X).z < 0.f) ? -m : m);                      \
        a = fabsf((X).w); m = (fabsf(a - m1.w) < 1e-9f) ? m2.w : m1.w;        \
        o.w = ALPHA_C * sg.w * (((X).w < 0.f) ? -m : m);                      \
        ((float4*)(g_ctv + (size_t)(E) * BB))[j] = o;                         \
    }
    EMIT(x0, e0) EMIT(x1, e1) EMIT(x2, e2) EMIT(x3, e3)
#undef EMIT
}

// Var side: vext = llr + (((a+b)+c)+d) (EXACT reference order), then write
// clamped vtc[e] = clamp(vext - ctv[e]) for each of the 4 edges.
// Block = 256 threads = 4 vars x 64 float4-lanes.
__global__ void k_varsum(const int* __restrict__ var_adj)
{
    int t = threadIdx.x;
    int v = blockIdx.x * 4 + (t >> 6);
    int j = t & 63;
    int4 e = __ldg((const int4*)var_adj + v);
    float4 a = ((const float4*)(g_ctv + (size_t)e.x * BB))[j];
    float4 b = ((const float4*)(g_ctv + (size_t)e.y * BB))[j];
    float4 c = ((const float4*)(g_ctv + (size_t)e.z * BB))[j];
    float4 d = ((const float4*)(g_ctv + (size_t)e.w * BB))[j];
    float4 l = ((const float4*)(g_llr_t + (size_t)v * BB))[j];
    float4 s;
    s.x = l.x + (((a.x + b.x) + c.x) + d.x);
    s.y = l.y + (((a.y + b.y) + c.y) + d.y);
    s.z = l.z + (((a.z + b.z) + c.z) + d.z);
    s.w = l.w + (((a.w + b.w) + c.w) + d.w);
    float4 o;
    o.x = clampv(s.x - a.x); o.y = clampv(s.y - a.y);
    o.z = clampv(s.z - a.z); o.w = clampv(s.w - a.w);
    ((float4*)(g_vtc + (size_t)e.x * BB))[j] = o;
    o.x = clampv(s.x - b.x); o.y = clampv(s.y - b.y);
    o.z = clampv(s.z - b.z); o.w = clampv(s.w - b.w);
    ((float4*)(g_vtc + (size_t)e.y * BB))[j] = o;
    o.x = clampv(s.x - c.x); o.y = clampv(s.y - c.y);
    o.z = clampv(s.z - c.z); o.w = clampv(s.w - c.w);
    ((float4*)(g_vtc + (size_t)e.z * BB))[j] = o;
    o.x = clampv(s.x - d.x); o.y = clampv(s.y - d.y);
    o.z = clampv(s.z - d.z); o.w = clampv(s.w - d.w);
    ((float4*)(g_vtc + (size_t)e.w * BB))[j] = o;
}

// Final (fused): total_llr = llr + sum(ctv); marginals + hard to d_out [B,N];
// hard also to g_hard [N,B]; block (0,0) initializes conv to 1.
__global__ void k_out(const int* __restrict__ var_adj,
                      float* __restrict__ out_marg,
                      float* __restrict__ out_hard,
                      float* __restrict__ conv)
{
    __shared__ float tile[32][33];
    int c0 = blockIdx.x * 32;   // batch tile
    int r0 = blockIdx.y * 32;   // var tile
    int c = c0 + threadIdx.x;   // batch index
    if (blockIdx.x == 0 && blockIdx.y == 0) {
        int t = threadIdx.y * 32 + threadIdx.x;
        conv[t] = 1.0f;
    }
    #pragma unroll
    for (int i = 0; i < 32; i += 8) {
        int v = r0 + threadIdx.y + i;      // uniform per warp
        int4 e = __ldg((const int4*)var_adj + v);
        float a = g_ctv[(size_t)e.x * BB + c];
        float b = g_ctv[(size_t)e.y * BB + c];
        float d0 = g_ctv[(size_t)e.z * BB + c];
        float d1 = g_ctv[(size_t)e.w * BB + c];
        float l = g_llr_t[(size_t)v * BB + c];
        float t = l + (((a + b) + d0) + d1);
        tile[threadIdx.y + i][threadIdx.x] = t;
        float marg = 1.0f / (1.0f + expf(t));
        g_hard[(size_t)v * BB + c] = (marg > 0.5f) ? 1.0f : 0.0f;
    }
    __syncthreads();
    int oc = r0 + threadIdx.x;            // var index in output
    #pragma unroll
    for (int i = 0; i < 32; i += 8) {
        int orow = c0 + threadIdx.y + i;  // batch index in output
        float t = tile[threadIdx.x][threadIdx.y + i];
        float marg = 1.0f / (1.0f + expf(t));
        size_t oi = (size_t)orow * NN + oc;
        out_marg[oi] = marg;
        out_hard[oi] = (marg > 0.5f) ? 1.0f : 0.0f;
    }
}

// Parity per (check, batch-quad): mismatch -> converged[b] = 0.
__global__ void k_parity(float* __restrict__ conv)
{
    int t = threadIdx.x;
    int c = blockIdx.x * 4 + (t >> 6);
    int j = t & 63;
    int deg = g_deg[c];
    const int* cv = g_cv + c * 32;
    int p0 = 0, p1 = 0, p2 = 0, p3 = 0;
    for (int p = 0; p < deg; p++) {
        int v = cv[p];
        float4 h = ((const float4*)(g_hard + (size_t)v * BB))[j];
        p0 += (int)h.x; p1 += (int)h.y; p2 += (int)h.z; p3 += (int)h.w;
    }
    float4 sg = ((const float4*)(g_ssign + (size_t)c * BB))[j];
    if ((p0 & 1) != (sg.x < 0.0f ? 1 : 0)) conv[j * 4 + 0] = 0.0f;
    if ((p1 & 1) != (sg.y < 0.0f ? 1 : 0)) conv[j * 4 + 1] = 0.0f;
    if ((p2 & 1) != (sg.z < 0.0f ? 1 : 0)) conv[j * 4 + 2] = 0.0f;
    if ((p3 & 1) != (sg.w < 0.0f ? 1 : 0)) conv[j * 4 + 3] = 0.0f;
}

// ---------------- launch ----------------------------------------------------

extern "C" void kernel_launch(void* const* d_in, const int* in_sizes, int n_in,
                              void* d_out, int out_size)
{
    const float* syndrome   = (const float*)d_in[0];   // [B, M]
    const float* llr        = (const float*)d_in[1];   // [B, N]
    const int*   var_adj    = (const int*)  d_in[2];   // [N, 4]
    const int*   check_adj  = (const int*)  d_in[4];   // [M, max_dc]
    const float* check_mask = (const float*)d_in[5];   // [M, max_dc]
    const int*   var_idx    = (const int*)  d_in[6];   // [E]

    const int max_dc = in_sizes[4] / MM;   // <= 32 for this code family
    float* out = (float*)d_out;
    size_t bn = (size_t)BB * NN;
    float* out_marg = out;            // [B, N]
    float* out_hard = out + bn;       // [B, N]
    float* out_conv = out + 2 * bn;   // [B]

    dim3 tb(32, 8);
    k_tr_llr<<<dim3(NN / 32, BB / 32), tb>>>(llr, var_adj);  // llr_t + iter0 vtc
    k_tr_syn<<<dim3(MM / 32, BB / 32), tb>>>(syndrome);      // ssign
    k_prep<<<(MM + 255) / 256, 256>>>(check_mask, check_adj, var_idx, max_dc);

    k_checkupd<<<MM * 2, 256>>>();
    for (int it = 1; it < N_ITERS; it++) {
        k_varsum<<<NN / 4, 256>>>(var_adj);
        k_checkupd<<<MM * 2, 256>>>();
    }

    k_out<<<dim3(BB / 32, NN / 32), tb>>>(var_adj, out_marg, out_hard, out_conv);
    k_parity<<<MM / 4, 256>>>(out_conv);
}

// round 13
// speedup vs baseline: 1.8171x; 1.8171x over previous
#include <cuda_runtime.h>
#include <math.h>

// Problem constants (fixed by the reference build)
#define MM   4096      // checks
#define NN   8192      // variables
#define BB   256       // batch
#define EE   32768     // edges  (NN * DV)
#define N_ITERS 10
#define ALPHA_C 0.8f
#define CLAMP_V 20.0f
#define PAD_BIG_C 1.0e6f

// ---------------- static device scratch (no allocations allowed) -----------
// vtc: var-major edge numbering  eid = v*4 + slot  ->  row [eid][B]
__device__ float g_vtc  [EE * BB];     // clamped var->check messages
__device__ float g_cmsg [MM * 3 * BB]; // per check: m1 row, m2 row, sgn row
__device__ float g_llr_t[NN * BB];     // transposed channel LLR, [N,B]
__device__ float g_ssign[MM * BB];     // 1-2*syndrome, [M,B]
__device__ float g_hard [NN * BB];     // hard decisions, [N,B] (for parity)
__device__ int   g_deg  [MM];          // check degrees
__device__ int   g_ce   [MM * 32];     // per check: translated eids (v*4+slot)
__device__ int   g_cv   [MM * 32];     // per check: var ids (parity)
__device__ int   g_vc   [NN * 4];      // per var slot: owning check id
__device__ int   g_pad;                // translated eid of reference edge 0

// ---------------- helpers ----------------------------------------------------
__device__ __forceinline__ float clampv(float x) {
    return fminf(fmaxf(x, -CLAMP_V), CLAMP_V);
}

// ---------------- kernels ---------------------------------------------------
// Device globals referenced only from device code (host shadow is not a dev ptr).

// Transpose llr [B,N] -> g_llr_t [N,B]; seed vtc rows (iter0: vtc = clamp(llr))
__global__ void k_tr_llr(const float* __restrict__ in)
{
    __shared__ float tile[32][33];
    int c0 = blockIdx.x * 32;   // N tile
    int r0 = blockIdx.y * 32;   // B tile
    int c = c0 + threadIdx.x;
    #pragma unroll
    for (int i = 0; i < 32; i += 8) {
        int r = r0 + threadIdx.y + i;
        tile[threadIdx.y + i][threadIdx.x] = in[(size_t)r * NN + c];
    }
    __syncthreads();
    int oc = r0 + threadIdx.x;            // batch index
    #pragma unroll
    for (int i = 0; i < 32; i += 8) {
        int v = c0 + threadIdx.y + i;     // var index (uniform per warp)
        float x = tile[threadIdx.x][threadIdx.y + i];
        g_llr_t[(size_t)v * BB + oc] = x;
        float cv = clampv(x);
        size_t base = (size_t)v * 4 * BB + oc;   // var-major vtc rows
        g_vtc[base]          = cv;
        g_vtc[base +     BB] = cv;
        g_vtc[base + 2 * BB] = cv;
        g_vtc[base + 3 * BB] = cv;
    }
}

// Transpose syndrome [B,M] -> g_ssign [M,B] with 1-2x.
__global__ void k_tr_syn(const float* __restrict__ in)
{
    __shared__ float tile[32][33];
    int c0 = blockIdx.x * 32;
    int r0 = blockIdx.y * 32;
    int c = c0 + threadIdx.x;
    #pragma unroll
    for (int i = 0; i < 32; i += 8) {
        int r = r0 + threadIdx.y + i;
        tile[threadIdx.y + i][threadIdx.x] = in[(size_t)r * MM + c];
    }
    __syncthreads();
    int oc = r0 + threadIdx.x;
    #pragma unroll
    for (int i = 0; i < 32; i += 8) {
        int orow = c0 + threadIdx.y + i;
        g_ssign[(size_t)orow * BB + oc] =
            1.0f - 2.0f * tile[threadIdx.x][threadIdx.y + i];
    }
}

// Prep: degrees, translated check slot tables, var->check table, pad eid.
__global__ void k_prep(const float* __restrict__ check_mask,
                       const int* __restrict__ check_adj,
                       const int* __restrict__ var_idx,
                       const int* __restrict__ var_adj,
                       int max_dc)
{
    int c = blockIdx.x * blockDim.x + threadIdx.x;
    if (c >= MM) return;
    if (c == 0) {
        int v0 = __ldg(var_idx);           // var of reference edge 0
        int s0 = 0;
        #pragma unroll
        for (int s = 0; s < 4; s++)
            if (__ldg(var_adj + v0 * 4 + s) == 0) s0 = s;
        g_pad = v0 * 4 + s0;
    }
    const float* m   = check_mask + (size_t)c * max_dc;
    const int*   adj = check_adj  + (size_t)c * max_dc;
    int d = 0;
    for (int j = 0; j < max_dc; j++) {
        if (__ldg(m + j) != 0.0f) {
            int e = __ldg(adj + j);
            int v = __ldg(var_idx + e);
            int s = 0;
            #pragma unroll
            for (int q = 0; q < 4; q++)
                if (__ldg(var_adj + v * 4 + q) == e) s = q;
            g_ce[c * 32 + d] = v * 4 + s;
            g_cv[c * 32 + d] = v;
            g_vc[v * 4 + s]  = c;
            d++;
        }
    }
    g_deg[c] = d;
}

// Check side: single pass — gather vtc rows, compute (m1, m2, sgn), write 3 rows.
// Block = 256 threads = 4 checks x 64 float4-lanes.
__global__ void __launch_bounds__(256) k_checkupd()
{
    int t = threadIdx.x;
    int c = blockIdx.x * 4 + (t >> 6);
    int j = t & 63;
    int deg = g_deg[c];
    if (deg == 0) return;
    const int* ce = g_ce + c * 32;

    float4 sg = ((const float4*)(g_ssign + (size_t)c * BB))[j];
    float4 m1, m2;
    if (deg == 1) {
        // reference pads with edge 0: seed = |vtc(pad)| + 1e6 (already clamped)
        float4 p0 = ((const float4*)(g_vtc + (size_t)g_pad * BB))[j];
        m1.x = fabsf(p0.x) + PAD_BIG_C;
        m1.y = fabsf(p0.y) + PAD_BIG_C;
        m1.z = fabsf(p0.z) + PAD_BIG_C;
        m1.w = fabsf(p0.w) + PAD_BIG_C;
    } else {
        m1.x = m1.y = m1.z = m1.w = 1.0e30f;   // pad can never win for deg>=2
    }
    m2 = m1;

    #pragma unroll 8
    for (int p = 0; p < deg; p++) {
        int e = ce[p];
        float4 x = ((const float4*)(g_vtc + (size_t)e * BB))[j];
        if (x.x < 0.0f) sg.x = -sg.x;
        if (x.y < 0.0f) sg.y = -sg.y;
        if (x.z < 0.0f) sg.z = -sg.z;
        if (x.w < 0.0f) sg.w = -sg.w;
        float a;
        a = fabsf(x.x); if (a < m1.x) { m2.x = m1.x; m1.x = a; } else if (a < m2.x) m2.x = a;
        a = fabsf(x.y); if (a < m1.y) { m2.y = m1.y; m1.y = a; } else if (a < m2.y) m2.y = a;
        a = fabsf(x.z); if (a < m1.z) { m2.z = m1.z; m1.z = a; } else if (a < m2.z) m2.z = a;
        a = fabsf(x.w); if (a < m1.w) { m2.w = m1.w; m1.w = a; } else if (a < m2.w) m2.w = a;
    }

    size_t base = (size_t)c * 3 * BB;
    ((float4*)(g_cmsg + base))[j]          = m1;
    ((float4*)(g_cmsg + base + BB))[j]     = m2;
    ((float4*)(g_cmsg + base + 2 * BB))[j] = sg;
}

// Reconstruct ctv for one slot from (old vtc, m1, m2, sgn).
__device__ __forceinline__ float4 recon(float4 o, float4 m1, float4 m2, float4 sg)
{
    float4 r; float a, m;
    a = fabsf(o.x); m = (fabsf(a - m1.x) < 1e-9f) ? m2.x : m1.x;
    r.x = ALPHA_C * sg.x * ((o.x < 0.0f) ? -m : m);
    a = fabsf(o.y); m = (fabsf(a - m1.y) < 1e-9f) ? m2.y : m1.y;
    r.y = ALPHA_C * sg.y * ((o.y < 0.0f) ? -m : m);
    a = fabsf(o.z); m = (fabsf(a - m1.z) < 1e-9f) ? m2.z : m1.z;
    r.z = ALPHA_C * sg.z * ((o.z < 0.0f) ? -m : m);
    a = fabsf(o.w); m = (fabsf(a - m1.w) < 1e-9f) ? m2.w : m1.w;
    r.w = ALPHA_C * sg.w * ((o.w < 0.0f) ? -m : m);
    return r;
}

// Var side: sequential own-row reads/writes; only cmsg triples are gathered.
// Block = 256 threads = 4 vars x 64 float4-lanes.
__global__ void __launch_bounds__(256) k_varsum()
{
    int t = threadIdx.x;
    int v = blockIdx.x * 4 + (t >> 6);
    int j = t & 63;
    size_t vb = (size_t)v * 4 * BB;
    float4 o0 = ((const float4*)(g_vtc + vb))[j];
    float4 o1 = ((const float4*)(g_vtc + vb + BB))[j];
    float4 o2 = ((const float4*)(g_vtc + vb + 2 * BB))[j];
    float4 o3 = ((const float4*)(g_vtc + vb + 3 * BB))[j];
    int4 ca = __ldg((const int4*)g_vc + v);

    size_t b0 = (size_t)ca.x * 3 * BB;
    size_t b1 = (size_t)ca.y * 3 * BB;
    size_t b2 = (size_t)ca.z * 3 * BB;
    size_t b3 = (size_t)ca.w * 3 * BB;
    float4 c0 = recon(o0, ((const float4*)(g_cmsg + b0))[j],
                          ((const float4*)(g_cmsg + b0 + BB))[j],
                          ((const float4*)(g_cmsg + b0 + 2 * BB))[j]);
    float4 c1 = recon(o1, ((const float4*)(g_cmsg + b1))[j],
                          ((const float4*)(g_cmsg + b1 + BB))[j],
                          ((const float4*)(g_cmsg + b1 + 2 * BB))[j]);
    float4 c2 = recon(o2, ((const float4*)(g_cmsg + b2))[j],
                          ((const float4*)(g_cmsg + b2 + BB))[j],
                          ((const float4*)(g_cmsg + b2 + 2 * BB))[j]);
    float4 c3 = recon(o3, ((const float4*)(g_cmsg + b3))[j],
                          ((const float4*)(g_cmsg + b3 + BB))[j],
                          ((const float4*)(g_cmsg + b3 + 2 * BB))[j]);

    float4 l = ((const float4*)(g_llr_t + (size_t)v * BB))[j];
    float4 s;   // EXACT reference order: llr + (((c0+c1)+c2)+c3)
    s.x = l.x + (((c0.x + c1.x) + c2.x) + c3.x);
    s.y = l.y + (((c0.y + c1.y) + c2.y) + c3.y);
    s.z = l.z + (((c0.z + c1.z) + c2.z) + c3.z);
    s.w = l.w + (((c0.w + c1.w) + c2.w) + c3.w);

    float4 o;
    o.x = clampv(s.x - c0.x); o.y = clampv(s.y - c0.y);
    o.z = clampv(s.z - c0.z); o.w = clampv(s.w - c0.w);
    ((float4*)(g_vtc + vb))[j] = o;
    o.x = clampv(s.x - c1.x); o.y = clampv(s.y - c1.y);
    o.z = clampv(s.z - c1.z); o.w = clampv(s.w - c1.w);
    ((float4*)(g_vtc + vb + BB))[j] = o;
    o.x = clampv(s.x - c2.x); o.y = clampv(s.y - c2.y);
    o.z = clampv(s.z - c2.z); o.w = clampv(s.w - c2.w);
    ((float4*)(g_vtc + vb + 2 * BB))[j] = o;
    o.x = clampv(s.x - c3.x); o.y = clampv(s.y - c3.y);
    o.z = clampv(s.z - c3.z); o.w = clampv(s.w - c3.w);
    ((float4*)(g_vtc + vb + 3 * BB))[j] = o;
}

// Scalar reconstruction helper for the output kernel.
__device__ __forceinline__ float recon1(float o, size_t cb, int b)
{
    float m1 = g_cmsg[cb + b];
    float m2 = g_cmsg[cb + BB + b];
    float sg = g_cmsg[cb + 2 * BB + b];
    float a = fabsf(o);
    float m = (fabsf(a - m1) < 1e-9f) ? m2 : m1;
    return ALPHA_C * sg * ((o < 0.0f) ? -m : m);
}

// Final: total_llr = llr + sum(reconstructed ctv); marginals + hard to d_out
// [B,N]; hard also to g_hard [N,B]; block (0,0) initializes conv to 1.
__global__ void k_out(float* __restrict__ out_marg,
                      float* __restrict__ out_hard,
                      float* __restrict__ conv)
{
    __shared__ float tile[32][33];
    int c0 = blockIdx.x * 32;   // batch tile
    int r0 = blockIdx.y * 32;   // var tile
    int c = c0 + threadIdx.x;   // batch index
    if (blockIdx.x == 0 && blockIdx.y == 0)
        conv[threadIdx.y * 32 + threadIdx.x] = 1.0f;
    #pragma unroll
    for (int i = 0; i < 32; i += 8) {
        int v = r0 + threadIdx.y + i;      // uniform per warp
        size_t vb = (size_t)v * 4 * BB;
        int4 ca = __ldg((const int4*)g_vc + v);
        float a0 = recon1(g_vtc[vb + c],          (size_t)ca.x * 3 * BB, c);
        float a1 = recon1(g_vtc[vb + BB + c],     (size_t)ca.y * 3 * BB, c);
        float a2 = recon1(g_vtc[vb + 2 * BB + c], (size_t)ca.z * 3 * BB, c);
        float a3 = recon1(g_vtc[vb + 3 * BB + c], (size_t)ca.w * 3 * BB, c);
        float l = g_llr_t[(size_t)v * BB + c];
        float tt = l + (((a0 + a1) + a2) + a3);
        tile[threadIdx.y + i][threadIdx.x] = tt;
        float marg = 1.0f / (1.0f + expf(tt));
        g_hard[(size_t)v * BB + c] = (marg > 0.5f) ? 1.0f : 0.0f;
    }
    __syncthreads();
    int oc = r0 + threadIdx.x;            // var index in output
    #pragma unroll
    for (int i = 0; i < 32; i += 8) {
        int orow = c0 + threadIdx.y + i;  // batch index in output
        float tt = tile[threadIdx.x][threadIdx.y + i];
        float marg = 1.0f / (1.0f + expf(tt));
        size_t oi = (size_t)orow * NN + oc;
        out_marg[oi] = marg;
        out_hard[oi] = (marg > 0.5f) ? 1.0f : 0.0f;
    }
}

// Parity per (check, batch-quad): mismatch -> converged[b] = 0.
__global__ void k_parity(float* __restrict__ conv)
{
    int t = threadIdx.x;
    int c = blockIdx.x * 4 + (t >> 6);
    int j = t & 63;
    int deg = g_deg[c];
    const int* cv = g_cv + c * 32;
    int p0 = 0, p1 = 0, p2 = 0, p3 = 0;
    for (int p = 0; p < deg; p++) {
        int v = cv[p];
        float4 h = ((const float4*)(g_hard + (size_t)v * BB))[j];
        p0 += (int)h.x; p1 += (int)h.y; p2 += (int)h.z; p3 += (int)h.w;
    }
    float4 sg = ((const float4*)(g_ssign + (size_t)c * BB))[j];
    if ((p0 & 1) != (sg.x < 0.0f ? 1 : 0)) conv[j * 4 + 0] = 0.0f;
    if ((p1 & 1) != (sg.y < 0.0f ? 1 : 0)) conv[j * 4 + 1] = 0.0f;
    if ((p2 & 1) != (sg.z < 0.0f ? 1 : 0)) conv[j * 4 + 2] = 0.0f;
    if ((p3 & 1) != (sg.w < 0.0f ? 1 : 0)) conv[j * 4 + 3] = 0.0f;
}

// ---------------- launch ----------------------------------------------------

extern "C" void kernel_launch(void* const* d_in, const int* in_sizes, int n_in,
                              void* d_out, int out_size)
{
    const float* syndrome   = (const float*)d_in[0];   // [B, M]
    const float* llr        = (const float*)d_in[1];   // [B, N]
    const int*   var_adj    = (const int*)  d_in[2];   // [N, 4]
    const int*   check_adj  = (const int*)  d_in[4];   // [M, max_dc]
    const float* check_mask = (const float*)d_in[5];   // [M, max_dc]
    const int*   var_idx    = (const int*)  d_in[6];   // [E]

    const int max_dc = in_sizes[4] / MM;   // <= 32 for this code family
    float* out = (float*)d_out;
    size_t bn = (size_t)BB * NN;
    float* out_marg = out;            // [B, N]
    float* out_hard = out + bn;       // [B, N]
    float* out_conv = out + 2 * bn;   // [B]

    dim3 tb(32, 8);
    k_tr_llr<<<dim3(NN / 32, BB / 32), tb>>>(llr);       // llr_t + iter0 vtc
    k_tr_syn<<<dim3(MM / 32, BB / 32), tb>>>(syndrome);  // ssign
    k_prep<<<(MM + 255) / 256, 256>>>(check_mask, check_adj, var_idx,
                                      var_adj, max_dc);

    k_checkupd<<<MM / 4, 256>>>();
    for (int it = 1; it < N_ITERS; it++) {
        k_varsum<<<NN / 4, 256>>>();
        k_checkupd<<<MM / 4, 256>>>();
    }

    k_out<<<dim3(BB / 32, NN / 32), tb>>>(out_marg, out_hard, out_conv);
    k_parity<<<MM / 4, 256>>>(out_conv);
}

// round 14
// speedup vs baseline: 1.8678x; 1.0279x over previous
#include <cuda_runtime.h>
#include <math.h>

// Problem constants (fixed by the reference build)
#define MM   4096      // checks
#define NN   8192      // variables
#define BB   256       // batch
#define EE   32768     // edges  (NN * DV)
#define N_ITERS 10
#define ALPHA_C 0.8f
#define CLAMP_V 20.0f
#define PAD_BIG_C 1.0e6f

// ---------------- static device scratch (no allocations allowed) -----------
__device__ float g_ctv  [EE * BB];   // check->var messages, edge-major [E,B]
__device__ float g_vtc  [EE * BB];   // clamped var->check messages, [E,B]
__device__ float g_llr_t[NN * BB];   // transposed channel LLR, [N,B]
__device__ float g_ssign[MM * BB];   // 1-2*syndrome, [M,B]
__device__ float g_hard [NN * BB];   // hard decisions, [N,B] (for parity)
__device__ int   g_deg  [MM];        // check degrees
__device__ int   g_ce   [MM * 32];   // per check: compacted edge ids
__device__ int   g_cv   [MM * 32];   // per check: compacted var ids (parity)

// ---------------- helpers ----------------------------------------------------
__device__ __forceinline__ float clampv(float x) {
    return fminf(fmaxf(x, -CLAMP_V), CLAMP_V);
}

// ---------------- kernels ---------------------------------------------------
// Device globals referenced only from device code (host shadow is not a dev ptr).

// Transpose llr [B,N] -> g_llr_t [N,B]; also seed g_vtc (iter0 ctv==0 so
// vtc[e] = clamp(llr[v]) for each of v's 4 edges).
__global__ void k_tr_llr(const float* __restrict__ in,
                         const int* __restrict__ var_adj)
{
    __shared__ float tile[32][33];
    int c0 = blockIdx.x * 32;   // N tile
    int r0 = blockIdx.y * 32;   // B tile
    int c = c0 + threadIdx.x;
    #pragma unroll
    for (int i = 0; i < 32; i += 8) {
        int r = r0 + threadIdx.y + i;
        tile[threadIdx.y + i][threadIdx.x] = in[(size_t)r * NN + c];
    }
    __syncthreads();
    int oc = r0 + threadIdx.x;            // batch index
    #pragma unroll
    for (int i = 0; i < 32; i += 8) {
        int v = c0 + threadIdx.y + i;     // var index (uniform per warp)
        float x = tile[threadIdx.x][threadIdx.y + i];
        g_llr_t[(size_t)v * BB + oc] = x;
        float cv = clampv(x);
        int4 e = __ldg((const int4*)var_adj + v);
        g_vtc[(size_t)e.x * BB + oc] = cv;
        g_vtc[(size_t)e.y * BB + oc] = cv;
        g_vtc[(size_t)e.z * BB + oc] = cv;
        g_vtc[(size_t)e.w * BB + oc] = cv;
    }
}

// Transpose syndrome [B,M] -> g_ssign [M,B] with 1-2x.
__global__ void k_tr_syn(const float* __restrict__ in)
{
    __shared__ float tile[32][33];
    int c0 = blockIdx.x * 32;
    int r0 = blockIdx.y * 32;
    int c = c0 + threadIdx.x;
    #pragma unroll
    for (int i = 0; i < 32; i += 8) {
        int r = r0 + threadIdx.y + i;
        tile[threadIdx.y + i][threadIdx.x] = in[(size_t)r * MM + c];
    }
    __syncthreads();
    int oc = r0 + threadIdx.x;
    #pragma unroll
    for (int i = 0; i < 32; i += 8) {
        int orow = c0 + threadIdx.y + i;
        g_ssign[(size_t)orow * BB + oc] =
            1.0f - 2.0f * tile[threadIdx.x][threadIdx.y + i];
    }
}

// Prep: per-check degree + compacted edge/var slot tables.
__global__ void k_prep(const float* __restrict__ check_mask,
                       const int* __restrict__ check_adj,
                       const int* __restrict__ var_idx,
                       int max_dc)
{
    int c = blockIdx.x * blockDim.x + threadIdx.x;
    if (c >= MM) return;
    const float* m   = check_mask + (size_t)c * max_dc;
    const int*   adj = check_adj  + (size_t)c * max_dc;
    int d = 0;
    for (int j = 0; j < max_dc; j++) {
        if (__ldg(m + j) != 0.0f) {
            int e = __ldg(adj + j);
            g_ce[c * 32 + d] = e;
            g_cv[c * 32 + d] = __ldg(var_idx + e);
            d++;
        }
    }
    g_deg[c] = d;
}

// Check side: min-sum update from the single vtc stream. R5 numerics exactly;
// float2 granularity: block = 512 threads = 4 checks x 128 float2-lanes.
// Total threads 2x the float4 version -> ~1.7 waves + more resident warps.
__global__ void __launch_bounds__(512) k_checkupd()
{
    int t = threadIdx.x;
    int c = blockIdx.x * 4 + (t >> 7);
    int j = t & 127;
    int deg = g_deg[c];
    if (deg == 0) return;
    const int* ce = g_ce + c * 32;

    float2 sg = ((const float2*)(g_ssign + (size_t)c * BB))[j];
    float2 m1, m2;
    if (deg == 1) {
        // reference pads with global edge 0: seed = |vtc(edge0)| + 1e6
        float2 p0 = ((const float2*)g_vtc)[j];   // row 0, already clamped
        m1.x = fabsf(p0.x) + PAD_BIG_C;
        m1.y = fabsf(p0.y) + PAD_BIG_C;
    } else {
        m1.x = m1.y = 1.0e30f;   // pad can never win for deg>=2
    }
    m2 = m1;

    // pass 1: sign product + two smallest magnitudes
    #pragma unroll 8
    for (int p = 0; p < deg; p++) {
        int e = ce[p];
        float2 x = ((const float2*)(g_vtc + (size_t)e * BB))[j];
        if (x.x < 0.0f) sg.x = -sg.x;
        if (x.y < 0.0f) sg.y = -sg.y;
        float a;
        a = fabsf(x.x); if (a < m1.x) { m2.x = m1.x; m1.x = a; } else if (a < m2.x) m2.x = a;
        a = fabsf(x.y); if (a < m1.y) { m2.y = m1.y; m1.y = a; } else if (a < m2.y) m2.y = a;
    }

    // pass 2: reload vtc (L1/L2-warm), write new messages
    #pragma unroll 8
    for (int p = 0; p < deg; p++) {
        int e = ce[p];
        float2 x = ((const float2*)(g_vtc + (size_t)e * BB))[j];
        float2 out;
        {
            float a = fabsf(x.x);
            float m = (fabsf(a - m1.x) < 1e-9f) ? m2.x : m1.x;
            out.x = ALPHA_C * sg.x * ((x.x < 0.0f) ? -m : m);
        }
        {
            float a = fabsf(x.y);
            float m = (fabsf(a - m1.y) < 1e-9f) ? m2.y : m1.y;
            out.y = ALPHA_C * sg.y * ((x.y < 0.0f) ? -m : m);
        }
        ((float2*)(g_ctv + (size_t)e * BB))[j] = out;
    }
}

// Var side: vext = llr + (((a+b)+c)+d) (EXACT reference order), then write
// clamped vtc[e] = clamp(vext - ctv[e]) for each of the 4 edges.
// Block = 256 threads = 4 vars x 64 float4-lanes.
__global__ void __launch_bounds__(256) k_varsum(const int* __restrict__ var_adj)
{
    int t = threadIdx.x;
    int v = blockIdx.x * 4 + (t >> 6);
    int j = t & 63;
    int4 e = __ldg((const int4*)var_adj + v);
    float4 a = ((const float4*)(g_ctv + (size_t)e.x * BB))[j];
    float4 b = ((const float4*)(g_ctv + (size_t)e.y * BB))[j];
    float4 c = ((const float4*)(g_ctv + (size_t)e.z * BB))[j];
    float4 d = ((const float4*)(g_ctv + (size_t)e.w * BB))[j];
    float4 l = ((const float4*)(g_llr_t + (size_t)v * BB))[j];
    float4 s;
    s.x = l.x + (((a.x + b.x) + c.x) + d.x);
    s.y = l.y + (((a.y + b.y) + c.y) + d.y);
    s.z = l.z + (((a.z + b.z) + c.z) + d.z);
    s.w = l.w + (((a.w + b.w) + c.w) + d.w);
    float4 o;
    o.x = clampv(s.x - a.x); o.y = clampv(s.y - a.y);
    o.z = clampv(s.z - a.z); o.w = clampv(s.w - a.w);
    ((float4*)(g_vtc + (size_t)e.x * BB))[j] = o;
    o.x = clampv(s.x - b.x); o.y = clampv(s.y - b.y);
    o.z = clampv(s.z - b.z); o.w = clampv(s.w - b.w);
    ((float4*)(g_vtc + (size_t)e.y * BB))[j] = o;
    o.x = clampv(s.x - c.x); o.y = clampv(s.y - c.y);
    o.z = clampv(s.z - c.z); o.w = clampv(s.w - c.w);
    ((float4*)(g_vtc + (size_t)e.z * BB))[j] = o;
    o.x = clampv(s.x - d.x); o.y = clampv(s.y - d.y);
    o.z = clampv(s.z - d.z); o.w = clampv(s.w - d.w);
    ((float4*)(g_vtc + (size_t)e.w * BB))[j] = o;
}

// Final (fused): total_llr = llr + sum(ctv); marginals + hard to d_out [B,N];
// hard also to g_hard [N,B]; block (0,0) initializes conv to 1.
__global__ void k_out(const int* __restrict__ var_adj,
                      float* __restrict__ out_marg,
                      float* __restrict__ out_hard,
                      float* __restrict__ conv)
{
    __shared__ float tile[32][33];
    int c0 = blockIdx.x * 32;   // batch tile
    int r0 = blockIdx.y * 32;   // var tile
    int c = c0 + threadIdx.x;   // batch index
    if (blockIdx.x == 0 && blockIdx.y == 0) {
        int t = threadIdx.y * 32 + threadIdx.x;
        conv[t] = 1.0f;
    }
    #pragma unroll
    for (int i = 0; i < 32; i += 8) {
        int v = r0 + threadIdx.y + i;      // uniform per warp
        int4 e = __ldg((const int4*)var_adj + v);
        float a = g_ctv[(size_t)e.x * BB + c];
        float b = g_ctv[(size_t)e.y * BB + c];
        float d0 = g_ctv[(size_t)e.z * BB + c];
        float d1 = g_ctv[(size_t)e.w * BB + c];
        float l = g_llr_t[(size_t)v * BB + c];
        float t = l + (((a + b) + d0) + d1);
        tile[threadIdx.y + i][threadIdx.x] = t;
        float marg = 1.0f / (1.0f + expf(t));
        g_hard[(size_t)v * BB + c] = (marg > 0.5f) ? 1.0f : 0.0f;
    }
    __syncthreads();
    int oc = r0 + threadIdx.x;            // var index in output
    #pragma unroll
    for (int i = 0; i < 32; i += 8) {
        int orow = c0 + threadIdx.y + i;  // batch index in output
        float t = tile[threadIdx.x][threadIdx.y + i];
        float marg = 1.0f / (1.0f + expf(t));
        size_t oi = (size_t)orow * NN + oc;
        out_marg[oi] = marg;
        out_hard[oi] = (marg > 0.5f) ? 1.0f : 0.0f;
    }
}

// Parity per (check, batch-quad): mismatch -> converged[b] = 0.
__global__ void k_parity(float* __restrict__ conv)
{
    int t = threadIdx.x;
    int c = blockIdx.x * 4 + (t >> 6);
    int j = t & 63;
    int deg = g_deg[c];
    const int* cv = g_cv + c * 32;
    int p0 = 0, p1 = 0, p2 = 0, p3 = 0;
    for (int p = 0; p < deg; p++) {
        int v = cv[p];
        float4 h = ((const float4*)(g_hard + (size_t)v * BB))[j];
        p0 += (int)h.x; p1 += (int)h.y; p2 += (int)h.z; p3 += (int)h.w;
    }
    float4 sg = ((const float4*)(g_ssign + (size_t)c * BB))[j];
    if ((p0 & 1) != (sg.x < 0.0f ? 1 : 0)) conv[j * 4 + 0] = 0.0f;
    if ((p1 & 1) != (sg.y < 0.0f ? 1 : 0)) conv[j * 4 + 1] = 0.0f;
    if ((p2 & 1) != (sg.z < 0.0f ? 1 : 0)) conv[j * 4 + 2] = 0.0f;
    if ((p3 & 1) != (sg.w < 0.0f ? 1 : 0)) conv[j * 4 + 3] = 0.0f;
}

// ---------------- launch ----------------------------------------------------

extern "C" void kernel_launch(void* const* d_in, const int* in_sizes, int n_in,
                              void* d_out, int out_size)
{
    const float* syndrome   = (const float*)d_in[0];   // [B, M]
    const float* llr        = (const float*)d_in[1];   // [B, N]
    const int*   var_adj    = (const int*)  d_in[2];   // [N, 4]
    const int*   check_adj  = (const int*)  d_in[4];   // [M, max_dc]
    const float* check_mask = (const float*)d_in[5];   // [M, max_dc]
    const int*   var_idx    = (const int*)  d_in[6];   // [E]

    const int max_dc = in_sizes[4] / MM;   // <= 32 for this code family
    float* out = (float*)d_out;
    size_t bn = (size_t)BB * NN;
    float* out_marg = out;            // [B, N]
    float* out_hard = out + bn;       // [B, N]
    float* out_conv = out + 2 * bn;   // [B]

    dim3 tb(32, 8);
    k_tr_llr<<<dim3(NN / 32, BB / 32), tb>>>(llr, var_adj);  // llr_t + iter0 vtc
    k_tr_syn<<<dim3(MM / 32, BB / 32), tb>>>(syndrome);      // ssign
    k_prep<<<(MM + 255) / 256, 256>>>(check_mask, check_adj, var_idx, max_dc);

    k_checkupd<<<MM / 4, 512>>>();
    for (int it = 1; it < N_ITERS; it++) {
        k_varsum<<<NN / 4, 256>>>(var_adj);
        k_checkupd<<<MM / 4, 512>>>();
    }

    k_out<<<dim3(BB / 32, NN / 32), tb>>>(var_adj, out_marg, out_hard, out_conv);
    k_parity<<<MM / 4, 256>>>(out_conv);
}